// round 3
// baseline (speedup 1.0000x reference)
#include <cuda_runtime.h>

#define NN 65536
#define EE 524288
#define GG 64

// ---------------- scratch (device globals; 16B-aligned for v4 access) ------
__device__ __align__(16) float g_deg[NN];
__device__ __align__(16) float g_dinv[NN];
__device__ __align__(16) float g_s1[NN];
__device__ __align__(16) float g_xw2[NN * 64];
__device__ __align__(16) float g_agg2[NN * 64];
__device__ __align__(16) float g_xw3[NN * 32];
__device__ __align__(16) float g_agg3[NN * 32];
__device__ __align__(16) float g_psum[GG * 32];
__device__ __align__(16) float g_pcnt[GG];

__device__ __forceinline__ void red_add_v4(float* p, float4 v) {
    asm volatile("red.global.add.v4.f32 [%0], {%1,%2,%3,%4};"
                 :: "l"(p), "f"(v.x), "f"(v.y), "f"(v.z), "f"(v.w)
                 : "memory");
}

// ---------------- init: zero accumulators, deg = 1 (self loop) -------------
__global__ void k_init() {
    int i = blockIdx.x * blockDim.x + threadIdx.x;   // grid covers NN*16
    float4 z = make_float4(0.f, 0.f, 0.f, 0.f);
    ((float4*)g_agg2)[i] = z;                         // NN*16 float4
    if (i < NN * 8) ((float4*)g_agg3)[i] = z;
    if (i < NN)     g_deg[i] = 1.0f;
    if (i < GG * 32) g_psum[i] = 0.f;
    if (i < GG)     g_pcnt[i] = 0.f;
}

// ---------------- degree ----------------------------------------------------
__global__ void k_deg(const int* __restrict__ ei) {
    int e = blockIdx.x * blockDim.x + threadIdx.x;
    if (e < EE) atomicAdd(&g_deg[ei[EE + e]], 1.0f);
}

__global__ void k_dinv(const float* __restrict__ x) {
    int i = blockIdx.x * blockDim.x + threadIdx.x;
    if (i < NN) {
        float d = rsqrtf(g_deg[i]);
        g_dinv[i] = d;
        g_s1[i] = x[i] * d * d;   // self-loop term of layer-1 scalar agg
    }
}

// ---------------- layer-1 scalar aggregation --------------------------------
__global__ void k_s1(const float* __restrict__ x, const int* __restrict__ ei) {
    int e = blockIdx.x * blockDim.x + threadIdx.x;
    if (e < EE) {
        int s = ei[e], d = ei[EE + e];
        atomicAdd(&g_s1[d], x[s] * g_dinv[s] * g_dinv[d]);
    }
}

// ---------------- mm2: xw2 = relu(s1*W1 + b1) @ W2  ([N,128]@[128,64]) ------
__global__ __launch_bounds__(256) void k_mm2(const float* __restrict__ W1,
                                             const float* __restrict__ b1,
                                             const float* __restrict__ W2) {
    __shared__ __align__(16) float W2s[128 * 64];       // 32 KB
    __shared__ __align__(16) float hrow[32][128];       // 16 KB
    int t = threadIdx.x;
    int rbase = blockIdx.x * 32;

    for (int i = t; i < 2048; i += 256)
        ((float4*)W2s)[i] = ((const float4*)W2)[i];
    for (int i = t; i < 32 * 128; i += 256) {
        int r = i >> 7, f = i & 127;
        hrow[r][f] = fmaxf(fmaf(g_s1[rbase + r], W1[f], b1[f]), 0.0f);
    }
    __syncthreads();

    int cg = t & 15, rp = t >> 4;     // 16 col-groups x 16 row-pairs
    int r0 = rp * 2;
    float4 a0 = make_float4(0.f, 0.f, 0.f, 0.f);
    float4 a1 = make_float4(0.f, 0.f, 0.f, 0.f);
#pragma unroll
    for (int k = 0; k < 128; k++) {
        float4 w = *(float4*)&W2s[k * 64 + cg * 4];
        float h0 = hrow[r0][k], h1 = hrow[r0 + 1][k];
        a0.x = fmaf(h0, w.x, a0.x); a0.y = fmaf(h0, w.y, a0.y);
        a0.z = fmaf(h0, w.z, a0.z); a0.w = fmaf(h0, w.w, a0.w);
        a1.x = fmaf(h1, w.x, a1.x); a1.y = fmaf(h1, w.y, a1.y);
        a1.z = fmaf(h1, w.z, a1.z); a1.w = fmaf(h1, w.w, a1.w);
    }
    *(float4*)&g_xw2[(rbase + r0) * 64 + cg * 4]     = a0;
    *(float4*)&g_xw2[(rbase + r0 + 1) * 64 + cg * 4] = a1;
}

// ---------------- scatter layer 2 (64-wide, v4 red) --------------------------
__global__ void k_scat2(const int* __restrict__ ei) {
    int t = blockIdx.x * blockDim.x + threadIdx.x;   // EE*16 threads exactly
    int e = t >> 4, q = t & 15;
    int s = ei[e], d = ei[EE + e];
    float nrm = g_dinv[s] * g_dinv[d];
    float4 v = *(float4*)&g_xw2[s * 64 + q * 4];
    v.x *= nrm; v.y *= nrm; v.z *= nrm; v.w *= nrm;
    red_add_v4(&g_agg2[d * 64 + q * 4], v);
}

// ---------------- mm3: xw3 = relu(agg2 + xw2*dinv^2 + b2) @ W3 --------------
__global__ __launch_bounds__(256) void k_mm3(const float* __restrict__ b2,
                                             const float* __restrict__ W3) {
    __shared__ __align__(16) float W3s[64 * 32];    // 8 KB
    __shared__ __align__(16) float hrow[64][64];    // 16 KB
    int t = threadIdx.x;
    int rbase = blockIdx.x * 64;

    for (int i = t; i < 512; i += 256)
        ((float4*)W3s)[i] = ((const float4*)W3)[i];
    for (int i = t; i < 64 * 64; i += 256) {
        int r = i >> 6, f = i & 63;
        int row = rbase + r;
        float di = g_dinv[row];
        hrow[r][f] = fmaxf(g_agg2[row * 64 + f] + g_xw2[row * 64 + f] * di * di + b2[f], 0.0f);
    }
    __syncthreads();

    int cg = t & 7, rp = t >> 3;      // 8 col-groups x 32 row-pairs
    int r0 = rp * 2;
    float4 a0 = make_float4(0.f, 0.f, 0.f, 0.f);
    float4 a1 = make_float4(0.f, 0.f, 0.f, 0.f);
#pragma unroll
    for (int k = 0; k < 64; k++) {
        float4 w = *(float4*)&W3s[k * 32 + cg * 4];
        float h0 = hrow[r0][k], h1 = hrow[r0 + 1][k];
        a0.x = fmaf(h0, w.x, a0.x); a0.y = fmaf(h0, w.y, a0.y);
        a0.z = fmaf(h0, w.z, a0.z); a0.w = fmaf(h0, w.w, a0.w);
        a1.x = fmaf(h1, w.x, a1.x); a1.y = fmaf(h1, w.y, a1.y);
        a1.z = fmaf(h1, w.z, a1.z); a1.w = fmaf(h1, w.w, a1.w);
    }
    *(float4*)&g_xw3[(rbase + r0) * 32 + cg * 4]     = a0;
    *(float4*)&g_xw3[(rbase + r0 + 1) * 32 + cg * 4] = a1;
}

// ---------------- scatter layer 3 (32-wide, v4 red) --------------------------
__global__ void k_scat3(const int* __restrict__ ei) {
    int t = blockIdx.x * blockDim.x + threadIdx.x;   // EE*8 threads exactly
    int e = t >> 3, q = t & 7;
    int s = ei[e], d = ei[EE + e];
    float nrm = g_dinv[s] * g_dinv[d];
    float4 v = *(float4*)&g_xw3[s * 32 + q * 4];
    v.x *= nrm; v.y *= nrm; v.z *= nrm; v.w *= nrm;
    red_add_v4(&g_agg3[d * 32 + q * 4], v);
}

// ---------------- pool: h3 on the fly, run-length segmented sum -------------
__global__ __launch_bounds__(256) void k_pool(const int* __restrict__ batch,
                                              const float* __restrict__ b3) {
    int t = threadIdx.x;
    int f = t & 31, s = t >> 5;          // 32 feats x 8 node streams
    const int NB = NN / 64;              // 1024 nodes per block, grid 64
    int base = blockIdx.x * NB;
    float bias = b3[f];

    float acc = 0.f, cnt = 0.f;
    int curb = batch[base + s];
#pragma unroll 4
    for (int i = 0; i < NB / 8; i++) {
        int node = base + s + i * 8;
        int b = batch[node];
        if (b != curb) {
            atomicAdd(&g_psum[curb * 32 + f], acc);
            if (f == 0) atomicAdd(&g_pcnt[curb], cnt);
            acc = 0.f; cnt = 0.f; curb = b;
        }
        float di = g_dinv[node];
        float v = fmaxf(g_agg3[node * 32 + f] + g_xw3[node * 32 + f] * di * di + bias, 0.0f);
        acc += v; cnt += 1.f;
    }
    atomicAdd(&g_psum[curb * 32 + f], acc);
    if (f == 0) atomicAdd(&g_pcnt[curb], cnt);
}

// ---------------- final FC: [64,32] @ [32,10] + bias -------------------------
__global__ void k_fc(const float* __restrict__ Wfc, const float* __restrict__ bfc,
                     float* __restrict__ out) {
    int t = threadIdx.x;
    if (t < GG * 10) {
        int g = t / 10, o = t % 10;
        float inv = 1.0f / fmaxf(g_pcnt[g], 1.0f);
        float acc = bfc[o];
#pragma unroll
        for (int f = 0; f < 32; f++)
            acc = fmaf(g_psum[g * 32 + f] * inv, Wfc[f * 10 + o], acc);
        out[g * 10 + o] = acc;
    }
}

// ---------------- launch ------------------------------------------------------
extern "C" void kernel_launch(void* const* d_in, const int* in_sizes, int n_in,
                              void* d_out, int out_size) {
    const float* x     = (const float*)d_in[0];
    const int*   ei    = (const int*)d_in[1];
    const int*   batch = (const int*)d_in[2];
    const float* W1    = (const float*)d_in[3];
    const float* b1    = (const float*)d_in[4];
    const float* W2    = (const float*)d_in[5];
    const float* b2    = (const float*)d_in[6];
    const float* W3    = (const float*)d_in[7];
    const float* b3    = (const float*)d_in[8];
    const float* Wfc   = (const float*)d_in[9];
    const float* bfc   = (const float*)d_in[10];
    float* out = (float*)d_out;

    k_init<<<(NN * 16) / 256, 256>>>();
    k_deg<<<EE / 256, 256>>>(ei);
    k_dinv<<<NN / 256, 256>>>(x);
    k_s1<<<EE / 256, 256>>>(x, ei);
    k_mm2<<<NN / 32, 256>>>(W1, b1, W2);
    k_scat2<<<(EE * 16) / 256, 256>>>(ei);
    k_mm3<<<NN / 64, 256>>>(b2, W3);
    k_scat3<<<(EE * 8) / 256, 256>>>(ei);
    k_pool<<<64, 256>>>(batch, b3);
    k_fc<<<1, 640>>>(Wfc, bfc, out);
}

// round 5
// speedup vs baseline: 1.2965x; 1.2965x over previous
#include <cuda_runtime.h>

#define NN 65536
#define EE 524288
#define GG 64

// ---------------- scratch ----------------------------------------------------
__device__ __align__(16) float g_deg[NN];
__device__ __align__(16) float g_dinv[NN];
__device__ __align__(16) float g_s1[NN];
__device__ __align__(16) int   g_base[NN];
__device__ __align__(16) int   g_cur[NN];
__device__ __align__(16) int2  g_meta[EE];       // {src, bitcast(norm)}
__device__ __align__(16) float g_xw2[NN * 64];
__device__ __align__(16) float g_h2in[NN * 64];
__device__ __align__(16) float g_xw3[NN * 32];
__device__ __align__(16) float g_h3in[NN * 32];
__device__ __align__(16) float g_psum[GG * 32];
__device__ __align__(16) float g_pcnt[GG];
__device__ int g_ctr;
// piecewise-linear table for xw2(s) = A[seg]*s + B[seg]
__device__ __align__(16) float g_knots[128];
__device__ __align__(16) float g_A[129 * 64];
__device__ __align__(16) float g_B[129 * 64];

// ---------------- init --------------------------------------------------------
__global__ void k_init() {
    int i = blockIdx.x * blockDim.x + threadIdx.x;   // NN threads
    g_deg[i] = 1.0f;                                  // self loop
    if (i < GG * 32) g_psum[i] = 0.f;
    if (i < GG)      g_pcnt[i] = 0.f;
    if (i == 0)      g_ctr = 0;
}

// ---------------- degree (4 edges / thread) ------------------------------------
__global__ void k_deg(const int* __restrict__ ei) {
    int t = blockIdx.x * blockDim.x + threadIdx.x;   // EE/4 threads
    int4 d4 = ((const int4*)(ei + EE))[t];
    atomicAdd(&g_deg[d4.x], 1.0f);
    atomicAdd(&g_deg[d4.y], 1.0f);
    atomicAdd(&g_deg[d4.z], 1.0f);
    atomicAdd(&g_deg[d4.w], 1.0f);
}

// ---------------- dinv + self term + CSR bases ---------------------------------
__global__ void k_dinv(const float* __restrict__ x) {
    int i = blockIdx.x * blockDim.x + threadIdx.x;
    float dg = g_deg[i];
    float d = rsqrtf(dg);
    g_dinv[i] = d;
    g_s1[i] = x[i] * d * d;            // layer-1 self-loop term
    int cnt = (int)dg - 1;             // in-degree (exact small float)
    int base = atomicAdd(&g_ctr, cnt);
    g_base[i] = base;
    g_cur[i]  = base;
}

// ---------------- CSR fill: per-edge {src, norm} grouped by dst ----------------
__global__ void k_fill(const int* __restrict__ ei) {
    int t = blockIdx.x * blockDim.x + threadIdx.x;   // EE/4 threads
    int4 s4 = ((const int4*)ei)[t];
    int4 d4 = ((const int4*)(ei + EE))[t];
#pragma unroll
    for (int k = 0; k < 4; k++) {
        int s = (k == 0) ? s4.x : (k == 1) ? s4.y : (k == 2) ? s4.z : s4.w;
        int d = (k == 0) ? d4.x : (k == 1) ? d4.y : (k == 2) ? d4.z : d4.w;
        float nrm = g_dinv[s] * g_dinv[d];
        int pos = atomicAdd(&g_cur[d], 1);
        g_meta[pos] = make_int2(s, __float_as_int(nrm));
    }
}

// ---------------- layer-1 scalar aggregation (gather) --------------------------
__global__ void k_s1g(const float* __restrict__ x) {
    int i = blockIdx.x * blockDim.x + threadIdx.x;   // NN threads
    float acc = g_s1[i];                             // self term
    int base = g_base[i];
    int cnt = (int)g_deg[i] - 1;
    for (int j = 0; j < cnt; j++) {
        int2 m = g_meta[base + j];
        acc = fmaf(x[m.x], __int_as_float(m.y), acc);
    }
    g_s1[i] = acc;
}

// ---------------- build piecewise-linear table for xw2(s) ----------------------
// xw2(s) = sum_f relu(s*W1[f]+b1[f]) * W2[f,:]  is PWL in s with knots -b1/W1.
__global__ void k_pw2(const float* __restrict__ W1, const float* __restrict__ b1,
                      const float* __restrict__ W2) {
    __shared__ float sw1[128], sb1[128], thr[128], sk[128];
    __shared__ int sidx[128];
    int t = threadIdx.x;                              // 128 threads
    float w = W1[t], b = b1[t];
    sw1[t] = w; sb1[t] = b;
    float th = (w != 0.f) ? (-b / w) : 3.4e38f;
    thr[t] = th;
    __syncthreads();
    int pos = 0;
    for (int j = 0; j < 128; j++) {
        float o = thr[j];
        pos += (o < th) || (o == th && j < t);
    }
    sk[pos] = th; sidx[pos] = t;
    __syncthreads();
    if (t < 128) g_knots[t] = sk[t];
    if (t < 64) {
        // initial active set at s = -inf: W1<0, plus constants (W1==0 && b1>0)
        float a = 0.f, bb = 0.f;
        for (int f = 0; f < 128; f++) {
            float w1 = sw1[f], b1v = sb1[f];
            if ((w1 < 0.f) || (w1 == 0.f && b1v > 0.f)) {
                float w2 = W2[f * 64 + t];
                a = fmaf(w1, w2, a); bb = fmaf(b1v, w2, bb);
            }
        }
        g_A[t] = a; g_B[t] = bb;
        // sweep knots in ascending order
        for (int j = 0; j < 128; j++) {
            int f = sidx[j]; float w1 = sw1[f];
            if (w1 > 0.f) {           // activates above knot
                float w2 = W2[f * 64 + t];
                a = fmaf(w1, w2, a); bb = fmaf(sb1[f], w2, bb);
            } else if (w1 < 0.f) {    // deactivates above knot
                float w2 = W2[f * 64 + t];
                a = fmaf(-w1, w2, a); bb = fmaf(-sb1[f], w2, bb);
            }
            g_A[(j + 1) * 64 + t] = a; g_B[(j + 1) * 64 + t] = bb;
        }
    }
}

// ---------------- evaluate xw2 = A[seg]*s + B[seg] ------------------------------
__global__ __launch_bounds__(256) void k_xw2() {
    __shared__ float sk[128];
    int t = threadIdx.x;
    if (t < 128) sk[t] = g_knots[t];
    __syncthreads();
    int gt = blockIdx.x * 256 + t;                    // NN*16 threads
    int node = gt >> 4, q = gt & 15;
    float s = g_s1[node];
    int seg = 0;                                      // count of knots < s
#pragma unroll
    for (int step = 128; step; step >>= 1) {          // FIX: reach seg=128
        int m = seg + step;
        if (m <= 128 && sk[m - 1] < s) seg = m;
    }
    float4 A = *(const float4*)&g_A[seg * 64 + q * 4];
    float4 B = *(const float4*)&g_B[seg * 64 + q * 4];
    float4 r;
    r.x = fmaf(A.x, s, B.x); r.y = fmaf(A.y, s, B.y);
    r.z = fmaf(A.z, s, B.z); r.w = fmaf(A.w, s, B.w);
    *(float4*)&g_xw2[node * 64 + q * 4] = r;
}

// ---------------- layer-2 aggregation: warp-per-node gather ---------------------
__global__ __launch_bounds__(256) void k_gat2() {
    int gw = (blockIdx.x * 256 + threadIdx.x) >> 5;   // node, NN warps
    int lane = threadIdx.x & 31;
    int base = g_base[gw];
    int cnt = (int)g_deg[gw] - 1;
    float di = g_dinv[gw], di2 = di * di;
    float2 xwv = *(const float2*)&g_xw2[gw * 64 + lane * 2];
    float2 acc = make_float2(xwv.x * di2, xwv.y * di2);   // self term
    const int2* mp = g_meta + base;
    for (int j = 0; j < cnt; j++) {
        int2 m = mp[j];
        float nrm = __int_as_float(m.y);
        float2 v = *(const float2*)&g_xw2[m.x * 64 + lane * 2];
        acc.x = fmaf(nrm, v.x, acc.x);
        acc.y = fmaf(nrm, v.y, acc.y);
    }
    *(float2*)&g_h2in[gw * 64 + lane * 2] = acc;
}

// ---------------- mm3: xw3 = relu(h2in + b2) @ W3 -------------------------------
__global__ __launch_bounds__(256) void k_mm3(const float* __restrict__ b2,
                                             const float* __restrict__ W3) {
    __shared__ __align__(16) float W3s[64 * 32];    // 8 KB
    __shared__ __align__(16) float hrow[64][64];    // 16 KB
    int t = threadIdx.x;
    int rbase = blockIdx.x * 64;

    for (int i = t; i < 512; i += 256)
        ((float4*)W3s)[i] = ((const float4*)W3)[i];
    for (int i = t; i < 64 * 64; i += 256) {
        int r = i >> 6, f = i & 63;
        hrow[r][f] = fmaxf(g_h2in[(rbase + r) * 64 + f] + b2[f], 0.0f);
    }
    __syncthreads();

    int cg = t & 7, rp = t >> 3;
    int r0 = rp * 2;
    float4 a0 = make_float4(0.f, 0.f, 0.f, 0.f);
    float4 a1 = make_float4(0.f, 0.f, 0.f, 0.f);
#pragma unroll
    for (int k = 0; k < 64; k++) {
        float4 w = *(float4*)&W3s[k * 32 + cg * 4];
        float h0 = hrow[r0][k], h1 = hrow[r0 + 1][k];
        a0.x = fmaf(h0, w.x, a0.x); a0.y = fmaf(h0, w.y, a0.y);
        a0.z = fmaf(h0, w.z, a0.z); a0.w = fmaf(h0, w.w, a0.w);
        a1.x = fmaf(h1, w.x, a1.x); a1.y = fmaf(h1, w.y, a1.y);
        a1.z = fmaf(h1, w.z, a1.z); a1.w = fmaf(h1, w.w, a1.w);
    }
    *(float4*)&g_xw3[(rbase + r0) * 32 + cg * 4]     = a0;
    *(float4*)&g_xw3[(rbase + r0 + 1) * 32 + cg * 4] = a1;
}

// ---------------- layer-3 aggregation: warp-per-node gather ---------------------
__global__ __launch_bounds__(256) void k_gat3() {
    int gw = (blockIdx.x * 256 + threadIdx.x) >> 5;
    int lane = threadIdx.x & 31;
    int base = g_base[gw];
    int cnt = (int)g_deg[gw] - 1;
    float di = g_dinv[gw], di2 = di * di;
    float acc = g_xw3[gw * 32 + lane] * di2;          // self term
    const int2* mp = g_meta + base;
    for (int j = 0; j < cnt; j++) {
        int2 m = mp[j];
        acc = fmaf(__int_as_float(m.y), g_xw3[m.x * 32 + lane], acc);
    }
    g_h3in[gw * 32 + lane] = acc;
}

// ---------------- pool: run-length segmented mean-sum ---------------------------
__global__ __launch_bounds__(256) void k_pool(const int* __restrict__ batch,
                                              const float* __restrict__ b3) {
    int t = threadIdx.x;
    int f = t & 31, s = t >> 5;
    const int NB = NN / 64;
    int base = blockIdx.x * NB;
    float bias = b3[f];

    float acc = 0.f, cnt = 0.f;
    int curb = batch[base + s];
#pragma unroll 4
    for (int i = 0; i < NB / 8; i++) {
        int node = base + s + i * 8;
        int b = batch[node];
        if (b != curb) {
            atomicAdd(&g_psum[curb * 32 + f], acc);
            if (f == 0) atomicAdd(&g_pcnt[curb], cnt);
            acc = 0.f; cnt = 0.f; curb = b;
        }
        float v = fmaxf(g_h3in[node * 32 + f] + bias, 0.0f);
        acc += v; cnt += 1.f;
    }
    atomicAdd(&g_psum[curb * 32 + f], acc);
    if (f == 0) atomicAdd(&g_pcnt[curb], cnt);
}

// ---------------- final FC -------------------------------------------------------
__global__ void k_fc(const float* __restrict__ Wfc, const float* __restrict__ bfc,
                     float* __restrict__ out) {
    int t = threadIdx.x;
    if (t < GG * 10) {
        int g = t / 10, o = t % 10;
        float inv = 1.0f / fmaxf(g_pcnt[g], 1.0f);
        float acc = bfc[o];
#pragma unroll
        for (int f = 0; f < 32; f++)
            acc = fmaf(g_psum[g * 32 + f] * inv, Wfc[f * 10 + o], acc);
        out[g * 10 + o] = acc;
    }
}

// ---------------- launch ----------------------------------------------------------
extern "C" void kernel_launch(void* const* d_in, const int* in_sizes, int n_in,
                              void* d_out, int out_size) {
    const float* x     = (const float*)d_in[0];
    const int*   ei    = (const int*)d_in[1];
    const int*   batch = (const int*)d_in[2];
    const float* W1    = (const float*)d_in[3];
    const float* b1    = (const float*)d_in[4];
    const float* W2    = (const float*)d_in[5];
    const float* b2    = (const float*)d_in[6];
    const float* W3    = (const float*)d_in[7];
    const float* b3    = (const float*)d_in[8];
    const float* Wfc   = (const float*)d_in[9];
    const float* bfc   = (const float*)d_in[10];
    float* out = (float*)d_out;

    k_init<<<NN / 256, 256>>>();
    k_deg <<<EE / 4 / 256, 256>>>(ei);
    k_dinv<<<NN / 256, 256>>>(x);
    k_fill<<<EE / 4 / 256, 256>>>(ei);
    k_s1g <<<NN / 256, 256>>>(x);
    k_pw2 <<<1, 128>>>(W1, b1, W2);
    k_xw2 <<<NN * 16 / 256, 256>>>();
    k_gat2<<<NN * 32 / 256, 256>>>();
    k_mm3 <<<NN / 64, 256>>>(b2, W3);
    k_gat3<<<NN * 32 / 256, 256>>>();
    k_pool<<<64, 256>>>(batch, b3);
    k_fc  <<<1, 640>>>(Wfc, bfc, out);
}